// round 2
// baseline (speedup 1.0000x reference)
#include <cuda_runtime.h>
#include <cstdint>
#include <cstddef>

#define OUT_FEAT 11008
#define IN_FEAT  4096
#define HAD      128
#define NBLK     (OUT_FEAT / HAD)   // 86
#define NTILE_N  (IN_FEAT / 128)    // 32

__device__ float g_W[(size_t)OUT_FEAT * (size_t)IN_FEAT];
__device__ unsigned int g_absmax_bits;

__global__ void k_init() {
    if (threadIdx.x == 0) g_absmax_bits = 0u;
}

// ---------------------------------------------------------------------------
// Kernel 1: rotation.  W[b*128+h, k] = sum_d R_right[d,h] * inp[b*128+d, k]
// (unchanged SIMT fp32; ~11.5 GFLOP total)
// ---------------------------------------------------------------------------
__global__ __launch_bounds__(256) void k_rotate(const float* __restrict__ inp,
                                                const float* __restrict__ Rr) {
    __shared__ float As[8][128];
    __shared__ float Bs[8][128];

    const int b   = blockIdx.y;
    const int nt  = blockIdx.x;
    const int tid = threadIdx.x;
    const int ty  = tid >> 4;
    const int tx  = tid & 15;
    const int ldR = tid >> 5;
    const int ldC = (tid & 31) << 2;

    const float* Bg = inp + ((size_t)b * HAD) * IN_FEAT + (size_t)nt * 128;

    float acc[8][8];
    #pragma unroll
    for (int i = 0; i < 8; i++)
        #pragma unroll
        for (int j = 0; j < 8; j++) acc[i][j] = 0.0f;

    float4 a_nxt = *(const float4*)&Rr[(size_t)ldR * HAD + ldC];
    float4 b_nxt = *(const float4*)&Bg[(size_t)ldR * IN_FEAT + ldC];

    for (int d0 = 0; d0 < HAD; d0 += 8) {
        *(float4*)&As[ldR][ldC] = a_nxt;
        *(float4*)&Bs[ldR][ldC] = b_nxt;
        __syncthreads();
        if (d0 + 8 < HAD) {
            a_nxt = *(const float4*)&Rr[(size_t)(d0 + 8 + ldR) * HAD + ldC];
            b_nxt = *(const float4*)&Bg[(size_t)(d0 + 8 + ldR) * IN_FEAT + ldC];
        }
        #pragma unroll
        for (int d = 0; d < 8; d++) {
            float a[8], bb[8];
            *(float4*)&a[0]  = *(float4*)&As[d][ty * 8];
            *(float4*)&a[4]  = *(float4*)&As[d][ty * 8 + 4];
            *(float4*)&bb[0] = *(float4*)&Bs[d][tx * 8];
            *(float4*)&bb[4] = *(float4*)&Bs[d][tx * 8 + 4];
            #pragma unroll
            for (int i = 0; i < 8; i++)
                #pragma unroll
                for (int j = 0; j < 8; j++)
                    acc[i][j] = fmaf(a[i], bb[j], acc[i][j]);
        }
        __syncthreads();
    }

    float* Cg = g_W + ((size_t)(b * HAD + ty * 8)) * IN_FEAT + (size_t)nt * 128 + tx * 8;
    #pragma unroll
    for (int i = 0; i < 8; i++) {
        *(float4*)&Cg[(size_t)i * IN_FEAT]     = make_float4(acc[i][0], acc[i][1], acc[i][2], acc[i][3]);
        *(float4*)&Cg[(size_t)i * IN_FEAT + 4] = make_float4(acc[i][4], acc[i][5], acc[i][6], acc[i][7]);
    }
}

// ---------------------------------------------------------------------------
// Kernel 2: tensor-core GEMM via 3xTF32.  Y = W @ R_left, absmax fused.
// CTA 128x128, BK=16, 8 warps (2Mx4N), warp tile 64x32, mma.m16n8k8.tf32.
// ---------------------------------------------------------------------------
__device__ __forceinline__ uint32_t tf32h(float x) {
    uint32_t u;
    asm("cvt.rna.tf32.f32 %0, %1;" : "=r"(u) : "f"(x));
    return u;
}

#define MMA_TF32(c, a, b)                                                      \
    asm volatile("mma.sync.aligned.m16n8k8.row.col.f32.tf32.tf32.f32 "         \
                 "{%0,%1,%2,%3},{%4,%5,%6,%7},{%8,%9},{%0,%1,%2,%3};"          \
                 : "+f"(c[0]), "+f"(c[1]), "+f"(c[2]), "+f"(c[3])              \
                 : "r"(a[0]), "r"(a[1]), "r"(a[2]), "r"(a[3]),                 \
                   "r"(b[0]), "r"(b[1]))

// smem word offsets (uint32 words)
#define AH_OFF 0
#define AL_OFF 2048
#define BH_OFF 4096
#define BL_OFF 6272
#define SM_WORDS 8448   // 33792 B

__device__ __forceinline__ float comp4(const float4& v, int e) {
    float r = v.x;
    r = (e == 1) ? v.y : r;
    r = (e == 2) ? v.z : r;
    r = (e == 3) ? v.w : r;
    return r;
}

__global__ __launch_bounds__(256) void k_gemm(const float* __restrict__ B,
                                              float* __restrict__ C) {
    __shared__ uint32_t sm[SM_WORDS];
    __shared__ float red[8];

    const int bm   = blockIdx.y;
    const int bn   = blockIdx.x;
    const int tid  = threadIdx.x;
    const int wid  = tid >> 5;
    const int lane = tid & 31;
    const int wm   = wid >> 2;   // 0..1
    const int wn   = wid & 3;    // 0..3

    // ---- loader constants ----
    // A: idx = tid + j*256 ; m = idx>>2 (0..127), kq = idx&3
    int mA[2], kqA[2], fbA[2];
    const float* Agp[2];
    #pragma unroll
    for (int j = 0; j < 2; j++) {
        int idx = tid + j * 256;
        mA[j]  = idx >> 2;
        kqA[j] = idx & 3;
        int ktA  = kqA[j] >> 1;
        int regA = ((kqA[j] & 1) << 1) + ((mA[j] >> 3) & 1);
        fbA[j] = ((ktA * 8 + (mA[j] >> 4)) * 128) + regA * 32 + (mA[j] & 7) * 4;
        Agp[j] = g_W + ((size_t)(bm * 128 + mA[j])) * IN_FEAT + kqA[j] * 4;
    }
    // B: idx = tid + j*256 ; k = idx>>5 (0..15), nq = idx&31
    int kB[2], qB[2], pB[2], fbB[2];
    const float* Bgp[2];
    #pragma unroll
    for (int j = 0; j < 2; j++) {
        int idx = tid + j * 256;
        kB[j] = idx >> 5;
        int nq = idx & 31;
        qB[j] = nq >> 1;
        pB[j] = nq & 1;
        int ktB  = kB[j] >> 3;
        int regB = (kB[j] >> 2) & 1;
        fbB[j] = (ktB * 16 + qB[j]) * 68 + regB * 34 + (kB[j] & 3);
        Bgp[j] = B + ((size_t)kB[j]) * IN_FEAT + (size_t)bn * 128 + nq * 4;
    }

    float acc[4][4][4];
    #pragma unroll
    for (int i = 0; i < 4; i++)
        #pragma unroll
        for (int j = 0; j < 4; j++)
            #pragma unroll
            for (int r = 0; r < 4; r++) acc[i][j][r] = 0.0f;

    float4 av[2], bv[2];
    #pragma unroll
    for (int j = 0; j < 2; j++) {
        av[j] = *(const float4*)Agp[j];
        bv[j] = *(const float4*)Bgp[j];
    }

    for (int k0 = 0; k0 < IN_FEAT; k0 += 16) {
        // ---- split + scatter into fragment-ordered smem ----
        #pragma unroll
        for (int j = 0; j < 2; j++) {
            #pragma unroll
            for (int e0 = 0; e0 < 4; e0++) {
                int e = (e0 + kqA[j]) & 3;       // rotated component walk (bank-free)
                float x = comp4(av[j], e);
                uint32_t hi = tf32h(x);
                uint32_t lo = tf32h(x - __uint_as_float(hi));
                sm[AH_OFF + fbA[j] + e] = hi;
                sm[AL_OFF + fbA[j] + e] = lo;
            }
            #pragma unroll
            for (int e0 = 0; e0 < 4; e0++) {
                int e = (e0 + qB[j]) & 3;
                float x = comp4(bv[j], e);
                int lane_f = (pB[j] * 4 + e) * 4;  // + (k&3) already in fbB
                uint32_t hi = tf32h(x);
                uint32_t lo = tf32h(x - __uint_as_float(hi));
                sm[BH_OFF + fbB[j] + lane_f] = hi;
                sm[BL_OFF + fbB[j] + lane_f] = lo;
            }
        }
        __syncthreads();

        if (k0 + 16 < IN_FEAT) {
            #pragma unroll
            for (int j = 0; j < 2; j++) {
                av[j] = *(const float4*)(Agp[j] + (k0 + 16));
                bv[j] = *(const float4*)(Bgp[j] + (size_t)(k0 + 16) * IN_FEAT);
            }
        }

        // ---- compute ----
        #pragma unroll
        for (int kt = 0; kt < 2; kt++) {
            uint32_t Bh_[4][2], Bl_[4][2];
            #pragma unroll
            for (int nt = 0; nt < 4; nt++) {
                int base = (kt * 16 + wn * 4 + nt) * 68 + lane;
                Bh_[nt][0] = sm[BH_OFF + base];
                Bh_[nt][1] = sm[BH_OFF + base + 34];
                Bl_[nt][0] = sm[BL_OFF + base];
                Bl_[nt][1] = sm[BL_OFF + base + 34];
            }
            #pragma unroll
            for (int mt = 0; mt < 4; mt++) {
                int base = (kt * 8 + wm * 4 + mt) * 128 + lane;
                uint32_t Ah_[4], Al_[4];
                #pragma unroll
                for (int r = 0; r < 4; r++) {
                    Ah_[r] = sm[AH_OFF + base + r * 32];
                    Al_[r] = sm[AL_OFF + base + r * 32];
                }
                #pragma unroll
                for (int nt = 0; nt < 4; nt++) {
                    MMA_TF32(acc[mt][nt], Ah_, Bh_[nt]);
                    MMA_TF32(acc[mt][nt], Ah_, Bl_[nt]);
                    MMA_TF32(acc[mt][nt], Al_, Bh_[nt]);
                }
            }
        }
        __syncthreads();
    }

    // ---- absmax ----
    float m = 0.0f;
    #pragma unroll
    for (int i = 0; i < 4; i++)
        #pragma unroll
        for (int j = 0; j < 4; j++)
            #pragma unroll
            for (int r = 0; r < 4; r++) m = fmaxf(m, fabsf(acc[i][j][r]));
    #pragma unroll
    for (int off = 16; off > 0; off >>= 1)
        m = fmaxf(m, __shfl_xor_sync(0xFFFFFFFFu, m, off));
    if (lane == 0) red[wid] = m;
    __syncthreads();
    if (tid == 0) {
        float mm = red[0];
        #pragma unroll
        for (int w = 1; w < 8; w++) mm = fmaxf(mm, red[w]);
        atomicMax(&g_absmax_bits, __float_as_uint(mm));
    }

    // ---- writeback (pre-quant Y) ----
    const int row0 = bm * 128 + wm * 64 + (lane >> 2);
    const int col0 = bn * 128 + wn * 32 + (lane & 3) * 2;
    #pragma unroll
    for (int mt = 0; mt < 4; mt++) {
        #pragma unroll
        for (int nt = 0; nt < 4; nt++) {
            float* p0 = C + (size_t)(row0 + mt * 16) * IN_FEAT + col0 + nt * 8;
            float* p1 = C + (size_t)(row0 + mt * 16 + 8) * IN_FEAT + col0 + nt * 8;
            *(float2*)p0 = make_float2(acc[mt][nt][0], acc[mt][nt][1]);
            *(float2*)p1 = make_float2(acc[mt][nt][2], acc[mt][nt][3]);
        }
    }
}

// ---------------------------------------------------------------------------
// Kernel 3: fake-quant in place (unchanged)
// ---------------------------------------------------------------------------
__global__ __launch_bounds__(256) void k_quant(float* __restrict__ y) {
    const float am = __uint_as_float(g_absmax_bits);
    const float s  = fmaxf(am * (1.0f / 127.0f), 1.17549435e-38f);
    size_t idx = (size_t)blockIdx.x * blockDim.x + threadIdx.x;
    float4 v = ((const float4*)y)[idx];
    float4 r;
    r.x = fminf(fmaxf(rintf(v.x / s), -127.0f), 127.0f) * s;
    r.y = fminf(fmaxf(rintf(v.y / s), -127.0f), 127.0f) * s;
    r.z = fminf(fmaxf(rintf(v.z / s), -127.0f), 127.0f) * s;
    r.w = fminf(fmaxf(rintf(v.w / s), -127.0f), 127.0f) * s;
    ((float4*)y)[idx] = r;
}

// ---------------------------------------------------------------------------
extern "C" void kernel_launch(void* const* d_in, const int* in_sizes, int n_in,
                              void* d_out, int out_size) {
    const float* inp     = (const float*)d_in[0];   // (11008, 4096)
    const float* R_left  = (const float*)d_in[1];   // (4096, 4096)
    const float* R_right = (const float*)d_in[2];   // (128, 128)
    float* out = (float*)d_out;                     // (11008, 4096)

    k_init<<<1, 32>>>();
    k_rotate<<<dim3(NTILE_N, NBLK), 256>>>(inp, R_right);
    k_gemm<<<dim3(NTILE_N, NBLK), 256>>>(R_left, out);

    const size_t n4 = ((size_t)OUT_FEAT * IN_FEAT) / 4;
    k_quant<<<(unsigned)(n4 / 256), 256>>>(out);
}

// round 4
// speedup vs baseline: 4.5925x; 4.5925x over previous
#include <cuda_runtime.h>
#include <cuda_bf16.h>
#include <cstdint>
#include <cstddef>

#define OUT_FEAT 11008
#define IN_FEAT  4096
#define HAD      128
#define NBLK     (OUT_FEAT / HAD)    // 86
#define NTILE    (IN_FEAT / 128)     // 32
#define MT_TOT   (OUT_FEAT / 16)     // 688 m16 tiles
#define KT_TOT   (IN_FEAT / 16)      // 256 k16 tiles
#define NT_TOT   (IN_FEAT / 8)       // 512 n8 tiles

// ---- fragment-packed operands (device globals: alloc-free rule) ----
// A block (m16 x k16): 64 uint4 = [lane 0..31: hi a0..a3][lane 0..31: lo a0..a3]
__device__ uint4 g_Wf[(size_t)MT_TOT * KT_TOT * 64];   // 180 MB
// B block (n8 x k16): 32 uint4 = [lane: b0h,b1h,b0l,b1l]
__device__ uint4 g_Bf[(size_t)NT_TOT * KT_TOT * 32];   // 67 MB
__device__ unsigned int g_absmax_bits;

__global__ void k_init() {
    if (threadIdx.x == 0) g_absmax_bits = 0u;
}

// split x = hi + lo (bf16 each); pack pairs (a even-col, b odd-col)
__device__ __forceinline__ void split_pack(float a, float b, uint32_t& h, uint32_t& l) {
    __nv_bfloat16 ha = __float2bfloat16_rn(a);
    __nv_bfloat16 hb = __float2bfloat16_rn(b);
    __nv_bfloat16 la = __float2bfloat16_rn(a - __bfloat162float(ha));
    __nv_bfloat16 lb = __float2bfloat16_rn(b - __bfloat162float(hb));
    h = ((uint32_t)__bfloat16_as_ushort(hb) << 16) | __bfloat16_as_ushort(ha);
    l = ((uint32_t)__bfloat16_as_ushort(lb) << 16) | __bfloat16_as_ushort(la);
}

// ---------------------------------------------------------------------------
// Kernel 1: rotation + split + fragment pack.
// W[b*128+h, k] = sum_d Rr[d,h] * inp[b*128+d, k];  tile (128h x 128k) per CTA.
// ---------------------------------------------------------------------------
__global__ __launch_bounds__(256) void k_rotate(const float* __restrict__ inp,
                                                const float* __restrict__ Rr) {
    __shared__ float As[8][128];
    __shared__ float Bs[8][128];
    extern __shared__ float T[];     // 128 x 130 staging

    const int b   = blockIdx.y;
    const int nt  = blockIdx.x;      // k-block of 128 (8 ktiles)
    const int tid = threadIdx.x;
    const int ty  = tid >> 4;
    const int tx  = tid & 15;
    const int ldR = tid >> 5;
    const int ldC = (tid & 31) << 2;

    const float* Bg = inp + ((size_t)b * HAD) * IN_FEAT + (size_t)nt * 128;

    float acc[8][8];
    #pragma unroll
    for (int i = 0; i < 8; i++)
        #pragma unroll
        for (int j = 0; j < 8; j++) acc[i][j] = 0.0f;

    float4 a_nxt = *(const float4*)&Rr[(size_t)ldR * HAD + ldC];
    float4 b_nxt = *(const float4*)&Bg[(size_t)ldR * IN_FEAT + ldC];

    for (int d0 = 0; d0 < HAD; d0 += 8) {
        *(float4*)&As[ldR][ldC] = a_nxt;
        *(float4*)&Bs[ldR][ldC] = b_nxt;
        __syncthreads();
        if (d0 + 8 < HAD) {
            a_nxt = *(const float4*)&Rr[(size_t)(d0 + 8 + ldR) * HAD + ldC];
            b_nxt = *(const float4*)&Bg[(size_t)(d0 + 8 + ldR) * IN_FEAT + ldC];
        }
        #pragma unroll
        for (int d = 0; d < 8; d++) {
            float a[8], bb[8];
            *(float4*)&a[0]  = *(float4*)&As[d][ty * 8];
            *(float4*)&a[4]  = *(float4*)&As[d][ty * 8 + 4];
            *(float4*)&bb[0] = *(float4*)&Bs[d][tx * 8];
            *(float4*)&bb[4] = *(float4*)&Bs[d][tx * 8 + 4];
            #pragma unroll
            for (int i = 0; i < 8; i++)
                #pragma unroll
                for (int j = 0; j < 8; j++)
                    acc[i][j] = fmaf(a[i], bb[j], acc[i][j]);
        }
        __syncthreads();
    }

    // stage fp32 tile
    #pragma unroll
    for (int i = 0; i < 8; i++)
        #pragma unroll
        for (int j = 0; j < 8; j++)
            T[(ty * 8 + i) * 130 + tx * 8 + j] = acc[i][j];
    __syncthreads();

    // fragment pack: 64 blocks (8 mt x 8 kt), 8 per warp
    const int wid  = tid >> 5;
    const int lane = tid & 31;
    const int r = lane >> 2;
    const int c = (lane & 3) * 2;
    #pragma unroll
    for (int t = 0; t < 8; t++) {
        int blk = wid * 8 + t;
        int mt = blk >> 3, kt = blk & 7;
        const float* p = &T[(mt * 16 + r) * 130 + kt * 16 + c];
        uint4 hi, lo;
        split_pack(p[0],           p[1],           hi.x, lo.x);
        split_pack(p[8 * 130],     p[8 * 130 + 1], hi.y, lo.y);
        split_pack(p[8],           p[9],           hi.z, lo.z);
        split_pack(p[8 * 130 + 8], p[8 * 130 + 9], hi.w, lo.w);
        size_t o = ((size_t)(b * 8 + mt) * KT_TOT + (nt * 8 + kt)) * 64;
        g_Wf[o + lane]      = hi;
        g_Wf[o + 32 + lane] = lo;
    }
}

// ---------------------------------------------------------------------------
// Kernel 2: pack R_left (K,N) into B fragments (n8 x k16 blocks)
// CTA: 64k x 64n region -> 8 n8-tiles x 4 k16-tiles.
// ---------------------------------------------------------------------------
__global__ __launch_bounds__(256) void k_packB(const float* __restrict__ R) {
    __shared__ float S[64][65];
    const int n0 = blockIdx.x * 64;
    const int k0 = blockIdx.y * 64;
    const int tid = threadIdx.x;

    #pragma unroll
    for (int j = 0; j < 16; j++) {
        int idx = tid + j * 256;
        int kk = idx >> 6, nn = idx & 63;
        S[kk][nn] = R[(size_t)(k0 + kk) * IN_FEAT + n0 + nn];
    }
    __syncthreads();

    const int wid  = tid >> 5;
    const int lane = tid & 31;
    const int n = lane >> 2;
    const int q = (lane & 3) * 2;
    #pragma unroll
    for (int t = 0; t < 4; t++) {
        int blk = wid * 4 + t;
        int ntl = blk >> 2, ktl = blk & 3;
        float x0 = S[ktl * 16 + q][ntl * 8 + n];
        float x1 = S[ktl * 16 + q + 1][ntl * 8 + n];
        float x2 = S[ktl * 16 + q + 8][ntl * 8 + n];
        float x3 = S[ktl * 16 + q + 9][ntl * 8 + n];
        uint4 v;
        split_pack(x0, x1, v.x, v.z);
        split_pack(x2, x3, v.y, v.w);
        size_t o = ((size_t)(blockIdx.x * 8 + ntl) * KT_TOT + (blockIdx.y * 4 + ktl)) * 32;
        g_Bf[o + lane] = v;
    }
}

// ---------------------------------------------------------------------------
// Kernel 3: main GEMM on bf16 mma.m16n8k16 with 3-product split.
// CTA 128x128, 8 warps (2m x 4n), k32 stages, 3-stage cp.async ring.
// ---------------------------------------------------------------------------
#define CP16(dst, src) asm volatile("cp.async.cg.shared.global [%0], [%1], 16;" :: "r"(dst), "l"(src))
#define CP_COMMIT()    asm volatile("cp.async.commit_group;" ::: "memory")
#define CP_WAIT1()     asm volatile("cp.async.wait_group 1;" ::: "memory")

#define LDS128(v, a) \
    asm volatile("ld.shared.v4.b32 {%0,%1,%2,%3}, [%4];" \
        : "=r"(v.x), "=r"(v.y), "=r"(v.z), "=r"(v.w) : "r"(a))

#define MMA_BF16(c, a, b0, b1)                                                 \
    asm volatile("mma.sync.aligned.m16n8k16.row.col.f32.bf16.bf16.f32 "        \
                 "{%0,%1,%2,%3},{%4,%5,%6,%7},{%8,%9},{%0,%1,%2,%3};"          \
                 : "+f"(c[0]), "+f"(c[1]), "+f"(c[2]), "+f"(c[3])              \
                 : "r"(a.x), "r"(a.y), "r"(a.z), "r"(a.w), "r"(b0), "r"(b1))

__device__ __forceinline__ uint32_t smem_u32(const void* p) {
    uint32_t a;
    asm("{ .reg .u64 t; cvta.to.shared.u64 t, %1; cvt.u32.u64 %0, t; }" : "=r"(a) : "l"(p));
    return a;
}

#define STAGE_BYTES 32768
#define GEMM_SMEM   (3 * STAGE_BYTES)   // 96 KB

__device__ __forceinline__ void load_stage(uint32_t su, int s, int i2, int tid,
                                           const uint4* __restrict__ Wsrc,
                                           const uint4* __restrict__ Bsrc) {
    const uint32_t sb = su + s * STAGE_BYTES;
    #pragma unroll
    for (int j = 0; j < 4; j++) {           // A: 1024 uint4
        int idx = tid + j * 256;
        int kth = idx >> 9, rem = idx & 511;
        int blk = rem >> 6, w = rem & 63;
        uint32_t dst = sb + kth * 8192 + blk * 1024 + w * 16;
        const uint4* src = Wsrc + ((size_t)blk * KT_TOT + (i2 * 2 + kth)) * 64 + w;
        CP16(dst, src);
    }
    #pragma unroll
    for (int j = 0; j < 4; j++) {           // B: 1024 uint4
        int idx = tid + j * 256;
        int kth = idx >> 9, rem = idx & 511;
        int blk = rem >> 5, w = rem & 31;
        uint32_t dst = sb + 16384 + kth * 8192 + blk * 512 + w * 16;
        const uint4* src = Bsrc + ((size_t)blk * KT_TOT + (i2 * 2 + kth)) * 32 + w;
        CP16(dst, src);
    }
}

__global__ __launch_bounds__(256, 2) void k_gemm(float* __restrict__ C) {
    extern __shared__ __align__(16) uint8_t smem[];
    __shared__ float red[8];
    const uint32_t su = smem_u32(smem);

    const int tid  = threadIdx.x;
    const int wid  = tid >> 5;
    const int lane = tid & 31;
    const int wm   = wid >> 2;
    const int wn   = wid & 3;

    // grid swizzle: 8bm x 32bn supertiles for L2 reuse
    const int lin = blockIdx.x;
    const int g   = lin >> 8;
    const int r_  = lin & 255;
    const int gsz = (NBLK - g * 8 < 8) ? (NBLK - g * 8) : 8;
    const int bm  = g * 8 + r_ % gsz;
    const int bn  = r_ / gsz;

    const uint4* Wsrc = g_Wf + (size_t)(bm * 8) * KT_TOT * 64;
    const uint4* Bsrc = g_Bf + (size_t)(bn * 16) * KT_TOT * 32;

    float acc[4][4][4];
    #pragma unroll
    for (int i = 0; i < 4; i++)
        #pragma unroll
        for (int j = 0; j < 4; j++)
            #pragma unroll
            for (int k = 0; k < 4; k++) acc[i][j][k] = 0.0f;

    load_stage(su, 0, 0, tid, Wsrc, Bsrc); CP_COMMIT();
    load_stage(su, 1, 1, tid, Wsrc, Bsrc); CP_COMMIT();

    for (int i2 = 0; i2 < KT_TOT / 2; i2++) {     // 128 k32 chunks
        const int s = i2 % 3;
        CP_WAIT1();
        __syncthreads();

        const uint32_t sb = su + s * STAGE_BYTES;
        #pragma unroll
        for (int kth = 0; kth < 2; kth++) {
            const uint32_t ab = sb + kth * 8192;
            const uint32_t bb = sb + 16384 + kth * 8192;
            uint4 bf[4];
            #pragma unroll
            for (int nt = 0; nt < 4; nt++)
                LDS128(bf[nt], bb + (wn * 4 + nt) * 512 + lane * 16);
            #pragma unroll
            for (int mt = 0; mt < 4; mt++) {
                uint4 ah, al;
                uint32_t aa = ab + (wm * 4 + mt) * 1024 + lane * 16;
                LDS128(ah, aa);
                LDS128(al, aa + 512);
                #pragma unroll
                for (int nt = 0; nt < 4; nt++) {
                    MMA_BF16(acc[mt][nt], ah, bf[nt].x, bf[nt].y);  // hi*hi
                    MMA_BF16(acc[mt][nt], ah, bf[nt].z, bf[nt].w);  // hi*lo
                    MMA_BF16(acc[mt][nt], al, bf[nt].x, bf[nt].y);  // lo*hi
                }
            }
        }

        if (i2 + 2 < KT_TOT / 2)
            load_stage(su, (i2 + 2) % 3, i2 + 2, tid, Wsrc, Bsrc);
        CP_COMMIT();
    }

    // absmax
    float m = 0.0f;
    #pragma unroll
    for (int i = 0; i < 4; i++)
        #pragma unroll
        for (int j = 0; j < 4; j++)
            #pragma unroll
            for (int k = 0; k < 4; k++) m = fmaxf(m, fabsf(acc[i][j][k]));
    #pragma unroll
    for (int off = 16; off > 0; off >>= 1)
        m = fmaxf(m, __shfl_xor_sync(0xFFFFFFFFu, m, off));
    if (lane == 0) red[wid] = m;
    __syncthreads();
    if (tid == 0) {
        float mm = red[0];
        #pragma unroll
        for (int w = 1; w < 8; w++) mm = fmaxf(mm, red[w]);
        atomicMax(&g_absmax_bits, __float_as_uint(mm));
    }

    // store pre-quant Y
    const int row0 = bm * 128 + wm * 64 + (lane >> 2);
    const int col0 = bn * 128 + wn * 32 + (lane & 3) * 2;
    #pragma unroll
    for (int mt = 0; mt < 4; mt++) {
        #pragma unroll
        for (int nt = 0; nt < 4; nt++) {
            float* p0 = C + (size_t)(row0 + mt * 16) * IN_FEAT + col0 + nt * 8;
            float* p1 = C + (size_t)(row0 + mt * 16 + 8) * IN_FEAT + col0 + nt * 8;
            *(float2*)p0 = make_float2(acc[mt][nt][0], acc[mt][nt][1]);
            *(float2*)p1 = make_float2(acc[mt][nt][2], acc[mt][nt][3]);
        }
    }
}

// ---------------------------------------------------------------------------
// Kernel 4: fake-quant in place
// ---------------------------------------------------------------------------
__global__ __launch_bounds__(256) void k_quant(float* __restrict__ y) {
    const float am = __uint_as_float(g_absmax_bits);
    const float s  = fmaxf(am * (1.0f / 127.0f), 1.17549435e-38f);
    size_t idx = (size_t)blockIdx.x * blockDim.x + threadIdx.x;
    float4 v = ((const float4*)y)[idx];
    float4 r;
    r.x = fminf(fmaxf(rintf(v.x / s), -127.0f), 127.0f) * s;
    r.y = fminf(fmaxf(rintf(v.y / s), -127.0f), 127.0f) * s;
    r.z = fminf(fmaxf(rintf(v.z / s), -127.0f), 127.0f) * s;
    r.w = fminf(fmaxf(rintf(v.w / s), -127.0f), 127.0f) * s;
    ((float4*)y)[idx] = r;
}

// ---------------------------------------------------------------------------
extern "C" void kernel_launch(void* const* d_in, const int* in_sizes, int n_in,
                              void* d_out, int out_size) {
    const float* inp     = (const float*)d_in[0];   // (11008, 4096)
    const float* R_left  = (const float*)d_in[1];   // (4096, 4096)
    const float* R_right = (const float*)d_in[2];   // (128, 128)
    float* out = (float*)d_out;                     // (11008, 4096)

    k_init<<<1, 32>>>();

    static int rot_smem_set = 0;
    const int ROT_SMEM = 128 * 130 * 4;   // 66560
    if (!rot_smem_set) {
        cudaFuncSetAttribute(k_rotate, cudaFuncAttributeMaxDynamicSharedMemorySize, ROT_SMEM);
        cudaFuncSetAttribute(k_gemm,  cudaFuncAttributeMaxDynamicSharedMemorySize, GEMM_SMEM);
        rot_smem_set = 1;
    }

    k_rotate<<<dim3(NTILE, NBLK), 256, ROT_SMEM>>>(inp, R_right);
    k_packB<<<dim3(IN_FEAT / 64, IN_FEAT / 64), 256>>>(R_left);
    k_gemm<<<NBLK * NTILE, 256, GEMM_SMEM>>>(out);

    const size_t n4 = ((size_t)OUT_FEAT * IN_FEAT) / 4;
    k_quant<<<(unsigned)(n4 / 256), 256>>>(out);
}

// round 5
// speedup vs baseline: 4.7786x; 1.0405x over previous
#include <cuda_runtime.h>
#include <cuda_bf16.h>
#include <cstdint>
#include <cstddef>

#define OUT_FEAT 11008
#define IN_FEAT  4096
#define HAD      128
#define NBLK     (OUT_FEAT / HAD)    // 86
#define MT_TOT   (OUT_FEAT / 16)     // 688 m16 tiles
#define KT_TOT   (IN_FEAT / 16)      // 256 k16 tiles
#define NT_TOT   (IN_FEAT / 8)       // 512 n8 tiles

// ---- fragment-packed operands (device globals: alloc-free rule) ----
// A block (m16 x k16): 64 uint4 = [lane 0..31: hi a0..a3][lane 0..31: lo a0..a3]
__device__ uint4 g_Wf[(size_t)MT_TOT * KT_TOT * 64];   // 180 MB
// B block (n8 x k16): 32 uint4 = [lane: b0h,b1h,b0l,b1l]
__device__ uint4 g_Bf[(size_t)NT_TOT * KT_TOT * 32];   // 67 MB
// Rr^T A-fragments: 8mt x 8kt blocks of 64 uint4 (64 KB)
__device__ uint4 g_Rf[64 * 64];
__device__ unsigned int g_absmax_bits;

// split x = hi + lo (bf16 each); pack pairs (a even-col, b odd-col)
__device__ __forceinline__ void split_pack(float a, float b, uint32_t& h, uint32_t& l) {
    __nv_bfloat16 ha = __float2bfloat16_rn(a);
    __nv_bfloat16 hb = __float2bfloat16_rn(b);
    __nv_bfloat16 la = __float2bfloat16_rn(a - __bfloat162float(ha));
    __nv_bfloat16 lb = __float2bfloat16_rn(b - __bfloat162float(hb));
    h = ((uint32_t)__bfloat16_as_ushort(hb) << 16) | __bfloat16_as_ushort(ha);
    l = ((uint32_t)__bfloat16_as_ushort(lb) << 16) | __bfloat16_as_ushort(la);
}

#define MMA_BF16(c, a, b0, b1)                                                 \
    asm volatile("mma.sync.aligned.m16n8k16.row.col.f32.bf16.bf16.f32 "        \
                 "{%0,%1,%2,%3},{%4,%5,%6,%7},{%8,%9},{%0,%1,%2,%3};"          \
                 : "+f"(c[0]), "+f"(c[1]), "+f"(c[2]), "+f"(c[3])              \
                 : "r"(a.x), "r"(a.y), "r"(a.z), "r"(a.w), "r"(b0), "r"(b1))

// ---------------------------------------------------------------------------
// Kernel 0: pack Rr^T into A-fragments (hi/lo bf16), once. Also zeroes absmax.
// A[h,d] = Rr[d,h].
// ---------------------------------------------------------------------------
__global__ void k_packRr(const float* __restrict__ Rr) {
    extern __shared__ float S[];   // 128 x 132
    const int tid = threadIdx.x;
    if (tid == 0) g_absmax_bits = 0u;
    #pragma unroll
    for (int j = 0; j < 64; j++) {
        int idx = tid + j * 256;
        S[(idx >> 7) * 132 + (idx & 127)] = Rr[idx];   // S[d][h]
    }
    __syncthreads();
    const int wid = tid >> 5, lane = tid & 31;
    const int r = lane >> 2, c = (lane & 3) * 2;
    #pragma unroll
    for (int t = 0; t < 8; t++) {
        int blk = wid * 8 + t;
        int mt = blk >> 3, kt = blk & 7;
        int R = mt * 16 + r;
        const float* p0 = &S[(kt * 16 + c) * 132 + R];       // A[R, c]   = Rr[c][R]
        const float* p1 = &S[(kt * 16 + c + 1) * 132 + R];   // A[R, c+1]
        uint4 hi, lo;
        split_pack(p0[0],           p1[0],           hi.x, lo.x);  // a0 (R,   c..c+1)
        split_pack(p0[8],           p1[8],           hi.y, lo.y);  // a1 (R+8, c..c+1)
        split_pack(p0[8 * 132],     p1[8 * 132],     hi.z, lo.z);  // a2 (R,   c+8..9)
        split_pack(p0[8 * 132 + 8], p1[8 * 132 + 8], hi.w, lo.w);  // a3 (R+8, c+8..9)
        g_Rf[blk * 64 + lane]      = hi;
        g_Rf[blk * 64 + 32 + lane] = lo;
    }
}

// ---------------------------------------------------------------------------
// Kernel 1: tensor-core rotation.  W[b*128+h, k] = sum_d Rr[d,h] * inp[b*128+d, k]
// CTA: 128h x 256k, 512 thr (16 warps: 2m x 8n), 4-product bf16 mma.
// Epilogue splits accumulators directly into g_Wf A-fragments.
// ---------------------------------------------------------------------------
#define RT_PITCH 260
#define ROT_SMEM (128 * RT_PITCH * 4 + 64 * 64 * 16)   // 133120 + 65536 = 198656

__global__ __launch_bounds__(512, 1) void k_rotate(const float* __restrict__ inp) {
    extern __shared__ float S[];                    // Sin[128][260]
    uint4* Rf = (uint4*)(S + 128 * RT_PITCH);       // 4096 uint4
    const int tid = threadIdx.x;
    const int b = blockIdx.y, ck = blockIdx.x;

    const float4* src = (const float4*)(inp + (size_t)b * 128 * IN_FEAT + ck * 256);
    #pragma unroll
    for (int j = 0; j < 16; j++) {
        int idx = tid + j * 512;                    // 8192 float4
        int d = idx >> 6, c4 = idx & 63;
        float4 v = src[(size_t)d * (IN_FEAT / 4) + c4];
        *(float4*)&S[d * RT_PITCH + c4 * 4] = v;
    }
    #pragma unroll
    for (int j = 0; j < 8; j++) {
        int idx = tid + j * 512;
        Rf[idx] = g_Rf[idx];
    }
    __syncthreads();

    const int wid = tid >> 5, lane = tid & 31;
    const int wm = wid >> 3, wn = wid & 7;
    const int q = (lane & 3) * 2;
    const int nbase = wn * 32 + (lane >> 2);

    float acc[4][4][4];
    #pragma unroll
    for (int i = 0; i < 4; i++)
        #pragma unroll
        for (int j = 0; j < 4; j++)
            #pragma unroll
            for (int k = 0; k < 4; k++) acc[i][j][k] = 0.0f;

    #pragma unroll 2
    for (int kt = 0; kt < 8; kt++) {
        uint32_t bh[4][2], bl[4][2];
        #pragma unroll
        for (int nt = 0; nt < 4; nt++) {
            const float* pp = &S[(kt * 16 + q) * RT_PITCH + nbase + nt * 8];
            split_pack(pp[0],            pp[RT_PITCH],     bh[nt][0], bl[nt][0]);
            split_pack(pp[8 * RT_PITCH], pp[9 * RT_PITCH], bh[nt][1], bl[nt][1]);
        }
        #pragma unroll
        for (int mt = 0; mt < 4; mt++) {
            int blk = (wm * 4 + mt) * 8 + kt;
            uint4 ah = Rf[blk * 64 + lane];
            uint4 al = Rf[blk * 64 + 32 + lane];
            #pragma unroll
            for (int nt = 0; nt < 4; nt++) {
                MMA_BF16(acc[mt][nt], ah, bh[nt][0], bh[nt][1]);
                MMA_BF16(acc[mt][nt], ah, bl[nt][0], bl[nt][1]);
                MMA_BF16(acc[mt][nt], al, bh[nt][0], bh[nt][1]);
                MMA_BF16(acc[mt][nt], al, bl[nt][0], bl[nt][1]);
            }
        }
    }

    // epilogue: accum fragment layout == A fragment layout; split-pack direct
    #pragma unroll
    for (int mt = 0; mt < 4; mt++) {
        #pragma unroll
        for (int u = 0; u < 2; u++) {
            float* c0 = acc[mt][u * 2];
            float* c1 = acc[mt][u * 2 + 1];
            uint4 hi, lo;
            split_pack(c0[0], c0[1], hi.x, lo.x);
            split_pack(c0[2], c0[3], hi.y, lo.y);
            split_pack(c1[0], c1[1], hi.z, lo.z);
            split_pack(c1[2], c1[3], hi.w, lo.w);
            size_t o = ((size_t)(b * 8 + wm * 4 + mt) * KT_TOT + (ck * 16 + wn * 2 + u)) * 64;
            g_Wf[o + lane]      = hi;
            g_Wf[o + 32 + lane] = lo;
        }
    }
}

// ---------------------------------------------------------------------------
// Kernel 2: pack R_left (K,N) into B fragments (n8 x k16 blocks)
// ---------------------------------------------------------------------------
__global__ __launch_bounds__(256) void k_packB(const float* __restrict__ R) {
    __shared__ float S[64][65];
    const int n0 = blockIdx.x * 64;
    const int k0 = blockIdx.y * 64;
    const int tid = threadIdx.x;

    #pragma unroll
    for (int j = 0; j < 16; j++) {
        int idx = tid + j * 256;
        int kk = idx >> 6, nn = idx & 63;
        S[kk][nn] = R[(size_t)(k0 + kk) * IN_FEAT + n0 + nn];
    }
    __syncthreads();

    const int wid  = tid >> 5;
    const int lane = tid & 31;
    const int n = lane >> 2;
    const int q = (lane & 3) * 2;
    #pragma unroll
    for (int t = 0; t < 4; t++) {
        int blk = wid * 4 + t;
        int ntl = blk >> 2, ktl = blk & 3;
        float x0 = S[ktl * 16 + q][ntl * 8 + n];
        float x1 = S[ktl * 16 + q + 1][ntl * 8 + n];
        float x2 = S[ktl * 16 + q + 8][ntl * 8 + n];
        float x3 = S[ktl * 16 + q + 9][ntl * 8 + n];
        uint4 v;
        split_pack(x0, x1, v.x, v.z);
        split_pack(x2, x3, v.y, v.w);
        size_t o = ((size_t)(blockIdx.x * 8 + ntl) * KT_TOT + (blockIdx.y * 4 + ktl)) * 32;
        g_Bf[o + lane] = v;
    }
}

// ---------------------------------------------------------------------------
// Kernel 3: main GEMM on bf16 mma.m16n8k16 with 3-product split.
// CTA 128x128, 8 warps (2m x 4n), k32 stages, 3-stage cp.async ring.
// ---------------------------------------------------------------------------
#define CP16(dst, src) asm volatile("cp.async.cg.shared.global [%0], [%1], 16;" :: "r"(dst), "l"(src))
#define CP_COMMIT()    asm volatile("cp.async.commit_group;" ::: "memory")
#define CP_WAIT1()     asm volatile("cp.async.wait_group 1;" ::: "memory")

#define LDS128(v, a) \
    asm volatile("ld.shared.v4.b32 {%0,%1,%2,%3}, [%4];" \
        : "=r"(v.x), "=r"(v.y), "=r"(v.z), "=r"(v.w) : "r"(a))

__device__ __forceinline__ uint32_t smem_u32(const void* p) {
    uint32_t a;
    asm("{ .reg .u64 t; cvta.to.shared.u64 t, %1; cvt.u32.u64 %0, t; }" : "=r"(a) : "l"(p));
    return a;
}

#define STAGE_BYTES 32768
#define GEMM_SMEM   (3 * STAGE_BYTES)   // 96 KB

__device__ __forceinline__ void load_stage(uint32_t su, int s, int i2, int tid,
                                           const uint4* __restrict__ Wsrc,
                                           const uint4* __restrict__ Bsrc) {
    const uint32_t sb = su + s * STAGE_BYTES;
    #pragma unroll
    for (int j = 0; j < 4; j++) {           // A: 1024 uint4
        int idx = tid + j * 256;
        int kth = idx >> 9, rem = idx & 511;
        int blk = rem >> 6, w = rem & 63;
        uint32_t dst = sb + kth * 8192 + blk * 1024 + w * 16;
        const uint4* src = Wsrc + ((size_t)blk * KT_TOT + (i2 * 2 + kth)) * 64 + w;
        CP16(dst, src);
    }
    #pragma unroll
    for (int j = 0; j < 4; j++) {           // B: 1024 uint4
        int idx = tid + j * 256;
        int kth = idx >> 9, rem = idx & 511;
        int blk = rem >> 5, w = rem & 31;
        uint32_t dst = sb + 16384 + kth * 8192 + blk * 512 + w * 16;
        const uint4* src = Bsrc + ((size_t)blk * KT_TOT + (i2 * 2 + kth)) * 32 + w;
        CP16(dst, src);
    }
}

__global__ __launch_bounds__(256, 2) void k_gemm(float* __restrict__ C) {
    extern __shared__ __align__(16) uint8_t smem[];
    __shared__ float red[8];
    const uint32_t su = smem_u32(smem);

    const int tid  = threadIdx.x;
    const int wid  = tid >> 5;
    const int lane = tid & 31;
    const int wm   = wid >> 2;
    const int wn   = wid & 3;

    // grid swizzle: 8bm x 32bn supertiles for L2 reuse
    const int lin = blockIdx.x;
    const int g   = lin >> 8;
    const int r_  = lin & 255;
    const int gsz = (NBLK - g * 8 < 8) ? (NBLK - g * 8) : 8;
    const int bm  = g * 8 + r_ % gsz;
    const int bn  = r_ / gsz;

    const uint4* Wsrc = g_Wf + (size_t)(bm * 8) * KT_TOT * 64;
    const uint4* Bsrc = g_Bf + (size_t)(bn * 16) * KT_TOT * 32;

    float acc[4][4][4];
    #pragma unroll
    for (int i = 0; i < 4; i++)
        #pragma unroll
        for (int j = 0; j < 4; j++)
            #pragma unroll
            for (int k = 0; k < 4; k++) acc[i][j][k] = 0.0f;

    load_stage(su, 0, 0, tid, Wsrc, Bsrc); CP_COMMIT();
    load_stage(su, 1, 1, tid, Wsrc, Bsrc); CP_COMMIT();

    for (int i2 = 0; i2 < KT_TOT / 2; i2++) {     // 128 k32 chunks
        const int s = i2 % 3;
        CP_WAIT1();
        __syncthreads();

        const uint32_t sb = su + s * STAGE_BYTES;
        #pragma unroll
        for (int kth = 0; kth < 2; kth++) {
            const uint32_t ab = sb + kth * 8192;
            const uint32_t bb = sb + 16384 + kth * 8192;
            uint4 bf[4];
            #pragma unroll
            for (int nt = 0; nt < 4; nt++)
                LDS128(bf[nt], bb + (wn * 4 + nt) * 512 + lane * 16);
            #pragma unroll
            for (int mt = 0; mt < 4; mt++) {
                uint4 ah, al;
                uint32_t aa = ab + (wm * 4 + mt) * 1024 + lane * 16;
                LDS128(ah, aa);
                LDS128(al, aa + 512);
                #pragma unroll
                for (int nt = 0; nt < 4; nt++) {
                    MMA_BF16(acc[mt][nt], ah, bf[nt].x, bf[nt].y);  // hi*hi
                    MMA_BF16(acc[mt][nt], ah, bf[nt].z, bf[nt].w);  // hi*lo
                    MMA_BF16(acc[mt][nt], al, bf[nt].x, bf[nt].y);  // lo*hi
                }
            }
        }

        if (i2 + 2 < KT_TOT / 2)
            load_stage(su, (i2 + 2) % 3, i2 + 2, tid, Wsrc, Bsrc);
        CP_COMMIT();
    }

    // absmax
    float m = 0.0f;
    #pragma unroll
    for (int i = 0; i < 4; i++)
        #pragma unroll
        for (int j = 0; j < 4; j++)
            #pragma unroll
            for (int k = 0; k < 4; k++) m = fmaxf(m, fabsf(acc[i][j][k]));
    #pragma unroll
    for (int off = 16; off > 0; off >>= 1)
        m = fmaxf(m, __shfl_xor_sync(0xFFFFFFFFu, m, off));
    if (lane == 0) red[wid] = m;
    __syncthreads();
    if (tid == 0) {
        float mm = red[0];
        #pragma unroll
        for (int w = 1; w < 8; w++) mm = fmaxf(mm, red[w]);
        atomicMax(&g_absmax_bits, __float_as_uint(mm));
    }

    // store pre-quant Y
    const int row0 = bm * 128 + wm * 64 + (lane >> 2);
    const int col0 = bn * 128 + wn * 32 + (lane & 3) * 2;
    #pragma unroll
    for (int mt = 0; mt < 4; mt++) {
        #pragma unroll
        for (int nt = 0; nt < 4; nt++) {
            float* p0 = C + (size_t)(row0 + mt * 16) * IN_FEAT + col0 + nt * 8;
            float* p1 = C + (size_t)(row0 + mt * 16 + 8) * IN_FEAT + col0 + nt * 8;
            *(float2*)p0 = make_float2(acc[mt][nt][0], acc[mt][nt][1]);
            *(float2*)p1 = make_float2(acc[mt][nt][2], acc[mt][nt][3]);
        }
    }
}

// ---------------------------------------------------------------------------
// Kernel 4: fake-quant in place
// ---------------------------------------------------------------------------
__global__ __launch_bounds__(256) void k_quant(float* __restrict__ y) {
    const float am = __uint_as_float(g_absmax_bits);
    const float s  = fmaxf(am * (1.0f / 127.0f), 1.17549435e-38f);
    size_t idx = (size_t)blockIdx.x * blockDim.x + threadIdx.x;
    float4 v = ((const float4*)y)[idx];
    float4 r;
    r.x = fminf(fmaxf(rintf(v.x / s), -127.0f), 127.0f) * s;
    r.y = fminf(fmaxf(rintf(v.y / s), -127.0f), 127.0f) * s;
    r.z = fminf(fmaxf(rintf(v.z / s), -127.0f), 127.0f) * s;
    r.w = fminf(fmaxf(rintf(v.w / s), -127.0f), 127.0f) * s;
    ((float4*)y)[idx] = r;
}

// ---------------------------------------------------------------------------
extern "C" void kernel_launch(void* const* d_in, const int* in_sizes, int n_in,
                              void* d_out, int out_size) {
    const float* inp     = (const float*)d_in[0];   // (11008, 4096)
    const float* R_left  = (const float*)d_in[1];   // (4096, 4096)
    const float* R_right = (const float*)d_in[2];   // (128, 128)
    float* out = (float*)d_out;                     // (11008, 4096)

    const int PACKRR_SMEM = 128 * 132 * 4;          // 67584
    cudaFuncSetAttribute(k_packRr, cudaFuncAttributeMaxDynamicSharedMemorySize, PACKRR_SMEM);
    cudaFuncSetAttribute(k_rotate, cudaFuncAttributeMaxDynamicSharedMemorySize, ROT_SMEM);
    cudaFuncSetAttribute(k_gemm,   cudaFuncAttributeMaxDynamicSharedMemorySize, GEMM_SMEM);

    k_packRr<<<1, 256, PACKRR_SMEM>>>(R_right);
    k_rotate<<<dim3(IN_FEAT / 256, NBLK), 512, ROT_SMEM>>>(inp);
    k_packB<<<dim3(IN_FEAT / 64, IN_FEAT / 64), 256>>>(R_left);
    k_gemm<<<NBLK * 32, 256, GEMM_SMEM>>>(out);

    const size_t n4 = ((size_t)OUT_FEAT * IN_FEAT) / 4;
    k_quant<<<(unsigned)(n4 / 256), 256>>>(out);
}